// round 7
// baseline (speedup 1.0000x reference)
#include <cuda_runtime.h>
#include <math.h>

// Problem constants (fixed shapes per reference)
#define TT 4096
#define HH 1024
#define EE 8
#define II 1024
#define KKtop 2
#define RTOT (TT*KKtop)   // 8192 routed rows total

#define TK 16

// gemm1 tile
#define G1_TM 128
#define G1_TN 64
// gemm2 tile
#define G2_TM 128
#define G2_TN 128

#define LDAD 260  // duplicated-A row stride (floats): 256 data + 4 pad, 1040B rows (16B aligned)
#define LDA  132  // padded stride for 128-wide smem tiles (floats); 528B rows, 16B aligned
#define LDB  68   // padded stride for 64-wide smem tiles; 272B rows, 16B aligned

// dynamic smem sizes (bytes)
#define G1_SMEM (2*(TK*LDAD + 2*TK*LDB)*4 + G1_TM*4)   // 2 A-bufs + 2x2 B-bufs + tok
#define G2_SMEM (2*(TK*LDAD + TK*LDA)*4)               // 2 A-bufs + 2 B-bufs

// ---------------- packed f32x2 helpers (Blackwell FFMA2 path) ----------------
__device__ __forceinline__ void unpack2(unsigned long long v, float& x, float& y) {
    asm("mov.b64 {%0, %1}, %2;" : "=f"(x), "=f"(y) : "l"(v));
}
// acc = a * b + acc, two independent IEEE f32 FMAs (bit-identical to FFMA)
#define FFMA2(acc, a, b) \
    asm("fma.rn.f32x2 %0, %1, %2, %0;" : "+l"(acc) : "l"(a), "l"(b))

// ---------------- scratch (static device globals; no allocations) ----------------
__device__ float d_hbuf[(size_t)RTOT * II];   // gelu(g)*u intermediate, 32 MB
__device__ int   d_row_token[RTOT];
__device__ float d_row_w[RTOT];
__device__ int   d_cnt[EE];
__device__ int   d_off[EE];
__device__ int   d_cur[EE];
__device__ int   d_top[TT * KKtop];
__device__ float d_cw[TT * KKtop];

// ---------------- small kernels ----------------
__global__ void zero_out_kernel(float4* out, int n4) {
    int i = blockIdx.x * blockDim.x + threadIdx.x;
    if (i < n4) out[i] = make_float4(0.f, 0.f, 0.f, 0.f);
}

__global__ void init_kernel() {
    int i = threadIdx.x;
    if (i < EE) { d_cnt[i] = 0; d_cur[i] = 0; }
}

// Per-token: softmax over 8 logits, top-2 (first index wins ties, matching
// jax.lax.top_k), renormalized combine weights * per_expert_scale.
__global__ void router_kernel(const float* __restrict__ logits,
                              const float* __restrict__ scale) {
    int t = blockIdx.x * blockDim.x + threadIdx.x;
    if (t >= TT) return;
    float l[EE];
#pragma unroll
    for (int e = 0; e < EE; e++) l[e] = logits[t * EE + e];

    int i1 = 0; float v1 = l[0];
#pragma unroll
    for (int e = 1; e < EE; e++) if (l[e] > v1) { v1 = l[e]; i1 = e; }
    int i2 = -1; float v2 = -3.0e38f;
#pragma unroll
    for (int e = 0; e < EE; e++) {
        if (e == i1) continue;
        if (l[e] > v2) { v2 = l[e]; i2 = e; }
    }
    float s = 0.0f;
#pragma unroll
    for (int e = 0; e < EE; e++) s += expf(l[e] - v1);
    float p1 = 1.0f / s;
    float p2 = expf(v2 - v1) / s;
    float rn = p1 + p2;

    d_top[t * 2 + 0] = i1;
    d_top[t * 2 + 1] = i2;
    d_cw[t * 2 + 0] = (p1 / rn) * scale[i1];
    d_cw[t * 2 + 1] = (p2 / rn) * scale[i2];
    atomicAdd(&d_cnt[i1], 1);
    atomicAdd(&d_cnt[i2], 1);
}

__global__ void scan_kernel() {
    if (threadIdx.x == 0) {
        int acc = 0;
        for (int e = 0; e < EE; e++) { d_off[e] = acc; acc += d_cnt[e]; }
    }
}

__global__ void assign_kernel() {
    int t = blockIdx.x * blockDim.x + threadIdx.x;
    if (t >= TT) return;
#pragma unroll
    for (int s = 0; s < KKtop; s++) {
        int e = d_top[t * 2 + s];
        int pos = atomicAdd(&d_cur[e], 1);
        int row = d_off[e] + pos;
        d_row_token[row] = t;
        d_row_w[row] = d_cw[t * 2 + s];
    }
}

// ---------------- GEMM 1: h = gelu(x@w1^T) * (x@w3^T), per expert segment ----
// 128x64 tile, 256 threads, per-thread 8 rows x 4 cols for BOTH g and u.
// Duplicated-A smem (LDS.128 -> broadcast pairs), FFMA2 inner loop,
// ping-pong double buffering: ONE barrier per k-tile.
__global__ void __launch_bounds__(256)
gemm1_kernel(const float* __restrict__ x,
             const float* __restrict__ w13) {
    extern __shared__ float smem[];
    float* Ad  = smem;                              // [2][TK*LDAD]
    float* B1s = Ad  + 2 * TK * LDAD;               // [2][TK*LDB]
    float* B3s = B1s + 2 * TK * LDB;                // [2][TK*LDB]
    int*   tok = (int*)(B3s + 2 * TK * LDB);        // [G1_TM]

    int e = blockIdx.z;
    int cnt = d_cnt[e];
    int rt = blockIdx.x * G1_TM;
    if (rt >= cnt) return;
    int it = blockIdx.y * G1_TN;
    int off = d_off[e];
    int rows_valid = min(G1_TM, cnt - rt);

    int tx = threadIdx.x, ty = threadIdx.y;
    int tid = ty * 16 + tx;
    int kk = tid & 15;        // k lane within tile (coalesced 64B per 16 lanes)
    int rbase = tid >> 4;     // 0..15

    if (tid < G1_TM)
        tok[tid] = (tid < rows_valid) ? d_row_token[off + rt + tid] : -1;
    __syncthreads();

    int mytok[8];
#pragma unroll
    for (int l = 0; l < 8; l++) mytok[l] = tok[rbase + l * 16];

    const float* w1base = w13 + (size_t)e * 2 * II * HH + (size_t)it * HH;
    const float* w3base = w1base + (size_t)II * HH;

    unsigned long long accg[8][2] = {};   // 8 rows x 2 col-pairs
    unsigned long long accu[8][2] = {};

    float pa[8], pb1[4], pb3[4];
    // prefetch tile 0
#pragma unroll
    for (int l = 0; l < 8; l++)
        pa[l] = (mytok[l] >= 0) ? x[(size_t)mytok[l] * HH + kk] : 0.0f;
#pragma unroll
    for (int l = 0; l < 4; l++) {
        int c = rbase + l * 16;
        pb1[l] = w1base[(size_t)c * HH + kk];
        pb3[l] = w3base[(size_t)c * HH + kk];
    }
    // commit tile 0 to buffer 0
#pragma unroll
    for (int l = 0; l < 8; l++) {
        int r = rbase + l * 16;
        *(float2*)&Ad[kk * LDAD + 2 * r] = make_float2(pa[l], pa[l]);
    }
#pragma unroll
    for (int l = 0; l < 4; l++) {
        B1s[kk * LDB + rbase + l * 16] = pb1[l];
        B3s[kk * LDB + rbase + l * 16] = pb3[l];
    }
    __syncthreads();

    int p = 0;
    for (int k0 = 0; k0 < HH; k0 += TK) {
        int kn = k0 + TK;
        if (kn < HH) {  // issue next tile's LDGs; land during compute
#pragma unroll
            for (int l = 0; l < 8; l++)
                pa[l] = (mytok[l] >= 0) ? x[(size_t)mytok[l] * HH + kn + kk] : 0.0f;
#pragma unroll
            for (int l = 0; l < 4; l++) {
                int c = rbase + l * 16;
                pb1[l] = w1base[(size_t)c * HH + kn + kk];
                pb3[l] = w3base[(size_t)c * HH + kn + kk];
            }
        }

        const float* Adp  = Ad  + p * TK * LDAD;
        const float* B1p  = B1s + p * TK * LDB;
        const float* B3p  = B3s + p * TK * LDB;
#pragma unroll
        for (int k = 0; k < TK; k++) {
            const float* adr = &Adp[k * LDAD + 16 * ty];
            ulonglong2 aq0 = *(const ulonglong2*)(adr);       // rows 0,1
            ulonglong2 aq1 = *(const ulonglong2*)(adr + 4);   // rows 2,3
            ulonglong2 aq2 = *(const ulonglong2*)(adr + 8);   // rows 4,5
            ulonglong2 aq3 = *(const ulonglong2*)(adr + 12);  // rows 6,7
            unsigned long long ap[8] = {aq0.x, aq0.y, aq1.x, aq1.y,
                                        aq2.x, aq2.y, aq3.x, aq3.y};
            ulonglong2 b1q = *(const ulonglong2*)&B1p[k * LDB + tx * 4];
            ulonglong2 b3q = *(const ulonglong2*)&B3p[k * LDB + tx * 4];
            unsigned long long b1p2[2] = {b1q.x, b1q.y};
            unsigned long long b3p2[2] = {b3q.x, b3q.y};
#pragma unroll
            for (int i = 0; i < 8; i++) {
#pragma unroll
                for (int j = 0; j < 2; j++) {
                    FFMA2(accg[i][j], ap[i], b1p2[j]);
                    FFMA2(accu[i][j], ap[i], b3p2[j]);
                }
            }
        }

        if (kn < HH) {  // store next tile into the other buffer, single barrier
            float* Adn  = Ad  + (1 - p) * TK * LDAD;
            float* B1n  = B1s + (1 - p) * TK * LDB;
            float* B3n  = B3s + (1 - p) * TK * LDB;
#pragma unroll
            for (int l = 0; l < 8; l++) {
                int r = rbase + l * 16;
                *(float2*)&Adn[kk * LDAD + 2 * r] = make_float2(pa[l], pa[l]);
            }
#pragma unroll
            for (int l = 0; l < 4; l++) {
                B1n[kk * LDB + rbase + l * 16] = pb1[l];
                B3n[kk * LDB + rbase + l * 16] = pb3[l];
            }
            __syncthreads();
            p ^= 1;
        }
    }

    float* hb = d_hbuf + (size_t)(off + rt) * II + it;
#pragma unroll
    for (int i = 0; i < 8; i++) {
        int r = ty * 8 + i;
        if (r < rows_valid) {
#pragma unroll
            for (int j = 0; j < 2; j++) {
                float g0, g1, u0, u1;
                unpack2(accg[i][j], g0, g1);
                unpack2(accu[i][j], u0, u1);
                int c = tx * 4 + j * 2;
                // exact gelu: 0.5*g*(1+erf(g/sqrt(2)))
                float h0 = 0.5f * g0 * (1.0f + erff(g0 * 0.70710678118654752f)) * u0;
                float h1 = 0.5f * g1 * (1.0f + erff(g1 * 0.70710678118654752f)) * u1;
                // adjacent columns -> one 64-bit store
                *(float2*)&hb[(size_t)r * II + c] = make_float2(h0, h1);
            }
        }
    }
}

// ---------------- GEMM 2: y = h @ w2^T, scaled-scatter into out --------------
// 128x128 tile, 256 threads, 8x8 per thread, duplicated-A + FFMA2,
// ping-pong double buffering. Each out element receives exactly 2
// commutative atomicAdds -> bit-deterministic across replays.
__global__ void __launch_bounds__(256)
gemm2_kernel(const float* __restrict__ w2,
             float* __restrict__ out) {
    extern __shared__ float smem[];
    float* Ad = smem;                    // [2][TK*LDAD]
    float* Bs = Ad + 2 * TK * LDAD;      // [2][TK*LDA]

    int e = blockIdx.z;
    int cnt = d_cnt[e];
    int rt = blockIdx.x * G2_TM;
    if (rt >= cnt) return;
    int ht = blockIdx.y * G2_TN;
    int off = d_off[e];
    int rows_valid = min(G2_TM, cnt - rt);

    int tx = threadIdx.x, ty = threadIdx.y;
    int tid = ty * 16 + tx;
    int kk = tid & 15;
    int rbase = tid >> 4;

    const float* abase = d_hbuf + (size_t)(off + rt) * II;
    const float* bbase = w2 + (size_t)e * HH * II + (size_t)ht * II;

    unsigned long long acc[8][4] = {};   // 8 rows x 4 col-pairs
    float pa[8], pb[8];

    // prefetch + commit tile 0 into buffer 0
#pragma unroll
    for (int l = 0; l < 8; l++) {
        int r = rbase + l * 16;
        pa[l] = (r < rows_valid) ? abase[(size_t)r * II + kk] : 0.0f;
        pb[l] = bbase[(size_t)r * II + kk];
    }
#pragma unroll
    for (int l = 0; l < 8; l++) {
        int r = rbase + l * 16;
        *(float2*)&Ad[kk * LDAD + 2 * r] = make_float2(pa[l], pa[l]);
        Bs[kk * LDA + r] = pb[l];
    }
    __syncthreads();

    int p = 0;
    for (int k0 = 0; k0 < II; k0 += TK) {
        int kn = k0 + TK;
        if (kn < II) {
#pragma unroll
            for (int l = 0; l < 8; l++) {
                int r = rbase + l * 16;
                pa[l] = (r < rows_valid) ? abase[(size_t)r * II + kn + kk] : 0.0f;
                pb[l] = bbase[(size_t)r * II + kn + kk];
            }
        }

        const float* Adp = Ad + p * TK * LDAD;
        const float* Bsp = Bs + p * TK * LDA;
#pragma unroll
        for (int k = 0; k < TK; k++) {
            const float* adr = &Adp[k * LDAD + 16 * ty];
            ulonglong2 aq0 = *(const ulonglong2*)(adr);
            ulonglong2 aq1 = *(const ulonglong2*)(adr + 4);
            ulonglong2 aq2 = *(const ulonglong2*)(adr + 8);
            ulonglong2 aq3 = *(const ulonglong2*)(adr + 12);
            unsigned long long ap[8] = {aq0.x, aq0.y, aq1.x, aq1.y,
                                        aq2.x, aq2.y, aq3.x, aq3.y};
            ulonglong2 bq0 = *(const ulonglong2*)&Bsp[k * LDA + tx * 8];
            ulonglong2 bq1 = *(const ulonglong2*)&Bsp[k * LDA + tx * 8 + 4];
            unsigned long long bp[4] = {bq0.x, bq0.y, bq1.x, bq1.y};
#pragma unroll
            for (int i = 0; i < 8; i++)
#pragma unroll
                for (int j = 0; j < 4; j++)
                    FFMA2(acc[i][j], ap[i], bp[j]);
        }

        if (kn < II) {
            float* Adn = Ad + (1 - p) * TK * LDAD;
            float* Bsn = Bs + (1 - p) * TK * LDA;
#pragma unroll
            for (int l = 0; l < 8; l++) {
                int r = rbase + l * 16;
                *(float2*)&Adn[kk * LDAD + 2 * r] = make_float2(pa[l], pa[l]);
                Bsn[kk * LDA + r] = pb[l];
            }
            __syncthreads();
            p ^= 1;
        }
    }

#pragma unroll
    for (int i = 0; i < 8; i++) {
        int r = ty * 8 + i;
        if (r < rows_valid) {
            int grow = off + rt + r;
            int t = d_row_token[grow];
            float w = d_row_w[grow];
#pragma unroll
            for (int j = 0; j < 4; j++) {
                float y0, y1;
                unpack2(acc[i][j], y0, y1);
                int c = ht + tx * 8 + j * 2;
                atomicAdd(&out[(size_t)t * HH + c],     w * y0);
                atomicAdd(&out[(size_t)t * HH + c + 1], w * y1);
            }
        }
    }
}

// ---------------- entry point ----------------
extern "C" void kernel_launch(void* const* d_in, const int* in_sizes, int n_in,
                              void* d_out, int out_size) {
    const float* x      = (const float*)d_in[0];
    const float* logits = (const float*)d_in[1];
    const float* scale  = (const float*)d_in[2];
    const float* w13    = (const float*)d_in[3];
    const float* w2     = (const float*)d_in[4];
    float* out = (float*)d_out;

    // Opt in to >48KB dynamic smem. Idempotent, non-stream API (legal under
    // graph capture, not an allocation). Called unconditionally every time —
    // no static guards per the harness contract.
    cudaFuncSetAttribute(gemm1_kernel,
                         cudaFuncAttributeMaxDynamicSharedMemorySize, G1_SMEM);
    cudaFuncSetAttribute(gemm2_kernel,
                         cudaFuncAttributeMaxDynamicSharedMemorySize, G2_SMEM);

    zero_out_kernel<<<(out_size / 4 + 255) / 256, 256>>>((float4*)out, out_size / 4);
    init_kernel<<<1, 32>>>();
    router_kernel<<<(TT + 255) / 256, 256>>>(logits, scale);
    scan_kernel<<<1, 1>>>();
    assign_kernel<<<(TT + 255) / 256, 256>>>();

    dim3 blk(16, 16);
    // grid.x covers worst case: one expert holding all 4096 tokens
    gemm1_kernel<<<dim3(TT / G1_TM, II / G1_TN, EE), blk, G1_SMEM>>>(x, w13);
    gemm2_kernel<<<dim3(TT / G2_TM, HH / G2_TN, EE), blk, G2_SMEM>>>(w2, out);
}

// round 10
// speedup vs baseline: 4.1167x; 4.1167x over previous
#include <cuda_runtime.h>
#include <math.h>
#include <stdint.h>

// Problem constants (fixed shapes per reference)
#define TT 4096
#define HH 1024
#define EE 8
#define II 1024
#define KKtop 2
#define RTOT (TT*KKtop)   // 8192 routed rows total

#define TKT 32            // k-tile depth
#define LDK 36            // padded k-stride in 4B words: 144B rows, 16B aligned,
                          // conflict-free fragment LDS ((4r+c) mod 32 distinct)

// gemm1: block tile 128(M) x 64(N), two outputs (g,u)
#define G1_TM 128
#define G1_TN 64
// gemm2: block tile 128(M) x 128(N)
#define G2_TM 128
#define G2_TN 128

// dynamic smem sizes (bytes)
#define G1_SMEM ((2*G1_TM*LDK + 2*G1_TN*LDK + 2*G1_TN*LDK)*4 + G1_TM*4)
#define G2_SMEM ((2*G2_TM*LDK + 2*G2_TM*LDK)*4)

// ---------------- tf32 mma helpers ----------------
__device__ __forceinline__ unsigned f2tf(float f) {
    unsigned u;
    asm("cvt.rna.tf32.f32 %0, %1;" : "=r"(u) : "f"(f));
    return u;
}
// D = A(16x8,tf32,row) * B(8x8,tf32,col) + D(fp32)
__device__ __forceinline__ void mma_tf32(float c[4], const unsigned a[4], const unsigned b[2]) {
    asm volatile(
        "mma.sync.aligned.m16n8k8.row.col.f32.tf32.tf32.f32 "
        "{%0,%1,%2,%3}, {%4,%5,%6,%7}, {%8,%9}, {%0,%1,%2,%3};"
        : "+f"(c[0]), "+f"(c[1]), "+f"(c[2]), "+f"(c[3])
        : "r"(a[0]), "r"(a[1]), "r"(a[2]), "r"(a[3]), "r"(b[0]), "r"(b[1]));
}

// ---------------- scratch (static device globals; no allocations) ----------------
__device__ float d_hbuf[(size_t)RTOT * II];   // gelu(g)*u intermediate, 32 MB
__device__ int   d_row_token[RTOT];
__device__ float d_row_w[RTOT];
__device__ int   d_cnt[EE];
__device__ int   d_off[EE];
__device__ int   d_cur[EE];
__device__ int   d_top[TT * KKtop];
__device__ float d_cw[TT * KKtop];

// ---------------- small kernels ----------------
__global__ void zero_out_kernel(float4* out, int n4) {
    int i = blockIdx.x * blockDim.x + threadIdx.x;
    if (i < n4) out[i] = make_float4(0.f, 0.f, 0.f, 0.f);
}

__global__ void init_kernel() {
    int i = threadIdx.x;
    if (i < EE) { d_cnt[i] = 0; d_cur[i] = 0; }
}

// Per-token: softmax over 8 logits, top-2 (first index wins ties, matching
// jax.lax.top_k), renormalized combine weights * per_expert_scale.
__global__ void router_kernel(const float* __restrict__ logits,
                              const float* __restrict__ scale) {
    int t = blockIdx.x * blockDim.x + threadIdx.x;
    if (t >= TT) return;
    float l[EE];
#pragma unroll
    for (int e = 0; e < EE; e++) l[e] = logits[t * EE + e];

    int i1 = 0; float v1 = l[0];
#pragma unroll
    for (int e = 1; e < EE; e++) if (l[e] > v1) { v1 = l[e]; i1 = e; }
    int i2 = -1; float v2 = -3.0e38f;
#pragma unroll
    for (int e = 0; e < EE; e++) {
        if (e == i1) continue;
        if (l[e] > v2) { v2 = l[e]; i2 = e; }
    }
    float s = 0.0f;
#pragma unroll
    for (int e = 0; e < EE; e++) s += expf(l[e] - v1);
    float p1 = 1.0f / s;
    float p2 = expf(v2 - v1) / s;
    float rn = p1 + p2;

    d_top[t * 2 + 0] = i1;
    d_top[t * 2 + 1] = i2;
    d_cw[t * 2 + 0] = (p1 / rn) * scale[i1];
    d_cw[t * 2 + 1] = (p2 / rn) * scale[i2];
    atomicAdd(&d_cnt[i1], 1);
    atomicAdd(&d_cnt[i2], 1);
}

__global__ void scan_kernel() {
    if (threadIdx.x == 0) {
        int acc = 0;
        for (int e = 0; e < EE; e++) { d_off[e] = acc; acc += d_cnt[e]; }
    }
}

__global__ void assign_kernel() {
    int t = blockIdx.x * blockDim.x + threadIdx.x;
    if (t >= TT) return;
#pragma unroll
    for (int s = 0; s < KKtop; s++) {
        int e = d_top[t * 2 + s];
        int pos = atomicAdd(&d_cur[e], 1);
        int row = d_off[e] + pos;
        d_row_token[row] = t;
        d_row_w[row] = d_cw[t * 2 + s];
    }
}

// ---------------- GEMM 1: h = gelu(x@w1^T) * (x@w3^T), per expert segment ----
// 128x64 tile, 256 threads = 8 warps in a 4(M)x2(N) grid; warp tile 32x32 for
// BOTH g and u. tf32 mma.sync m16n8k8, fp32 accumulate. Inputs cvt.rna to tf32
// once at STS. Ping-pong double buffering, one barrier per 32-k tile.
__global__ void __launch_bounds__(256)
gemm1_kernel(const float* __restrict__ x,
             const float* __restrict__ w13) {
    extern __shared__ unsigned smem_u[];
    unsigned* As  = smem_u;                          // [2][G1_TM*LDK]
    unsigned* B1s = As  + 2 * G1_TM * LDK;           // [2][G1_TN*LDK]
    unsigned* B3s = B1s + 2 * G1_TN * LDK;           // [2][G1_TN*LDK]
    int*      tok = (int*)(B3s + 2 * G1_TN * LDK);   // [G1_TM]

    int e = blockIdx.z;
    int cnt = d_cnt[e];
    int rt = blockIdx.x * G1_TM;
    if (rt >= cnt) return;
    int it = blockIdx.y * G1_TN;
    int off = d_off[e];
    int rows_valid = min(G1_TM, cnt - rt);

    int tid = threadIdx.x;
    int lane = tid & 31, warp = tid >> 5;
    int wm = warp >> 1, wn = warp & 1;   // warp tile origin (wm*32, wn*32)
    int gid = lane >> 2, qid = lane & 3;

    // loader mapping: A rows lr+{0,32,64,96}, B rows lr+{0,32}; k-quad lk
    int lr = tid >> 3;          // 0..31
    int lk = (tid & 7) * 4;     // 0,4,...,28

    if (tid < G1_TM)
        tok[tid] = (tid < rows_valid) ? d_row_token[off + rt + tid] : -1;
    __syncthreads();

    int mytok[4];
#pragma unroll
    for (int q = 0; q < 4; q++) mytok[q] = tok[lr + 32 * q];

    const float* w1base = w13 + (size_t)e * 2 * II * HH + (size_t)it * HH;
    const float* w3base = w1base + (size_t)II * HH;

    float cg[2][4][4], cu[2][4][4];
#pragma unroll
    for (int mt = 0; mt < 2; mt++)
#pragma unroll
        for (int nt = 0; nt < 4; nt++)
#pragma unroll
            for (int v = 0; v < 4; v++) { cg[mt][nt][v] = 0.f; cu[mt][nt][v] = 0.f; }

    float4 pa[4], pb1[2], pb3[2];

    // ---- prefetch k0 = 0 ----
#pragma unroll
    for (int q = 0; q < 4; q++)
        pa[q] = (mytok[q] >= 0) ? *(const float4*)&x[(size_t)mytok[q] * HH + lk]
                                : make_float4(0.f, 0.f, 0.f, 0.f);
#pragma unroll
    for (int q = 0; q < 2; q++) {
        int n = lr + 32 * q;
        pb1[q] = *(const float4*)&w1base[(size_t)n * HH + lk];
        pb3[q] = *(const float4*)&w3base[(size_t)n * HH + lk];
    }
    // ---- commit tile 0 to buffer 0 (cvt to tf32) ----
#pragma unroll
    for (int q = 0; q < 4; q++) {
        int r = lr + 32 * q;
        uint4 v = {f2tf(pa[q].x), f2tf(pa[q].y), f2tf(pa[q].z), f2tf(pa[q].w)};
        *(uint4*)&As[r * LDK + lk] = v;
    }
#pragma unroll
    for (int q = 0; q < 2; q++) {
        int n = lr + 32 * q;
        uint4 v1 = {f2tf(pb1[q].x), f2tf(pb1[q].y), f2tf(pb1[q].z), f2tf(pb1[q].w)};
        uint4 v3 = {f2tf(pb3[q].x), f2tf(pb3[q].y), f2tf(pb3[q].z), f2tf(pb3[q].w)};
        *(uint4*)&B1s[n * LDK + lk] = v1;
        *(uint4*)&B3s[n * LDK + lk] = v3;
    }
    __syncthreads();

    int p = 0;
    for (int k0 = 0; k0 < HH; k0 += TKT) {
        int kn = k0 + TKT;
        if (kn < HH) {  // issue next tile's LDGs; land during mma compute
#pragma unroll
            for (int q = 0; q < 4; q++)
                pa[q] = (mytok[q] >= 0)
                      ? *(const float4*)&x[(size_t)mytok[q] * HH + kn + lk]
                      : make_float4(0.f, 0.f, 0.f, 0.f);
#pragma unroll
            for (int q = 0; q < 2; q++) {
                int n = lr + 32 * q;
                pb1[q] = *(const float4*)&w1base[(size_t)n * HH + kn + lk];
                pb3[q] = *(const float4*)&w3base[(size_t)n * HH + kn + lk];
            }
        }

        const unsigned* Ab  = As  + p * G1_TM * LDK;
        const unsigned* B1b = B1s + p * G1_TN * LDK;
        const unsigned* B3b = B3s + p * G1_TN * LDK;
#pragma unroll
        for (int ks = 0; ks < TKT / 8; ks++) {
            unsigned a[2][4];
#pragma unroll
            for (int mt = 0; mt < 2; mt++) {
                const unsigned* ap = Ab + (wm * 32 + mt * 16 + gid) * LDK + ks * 8 + qid;
                a[mt][0] = ap[0];
                a[mt][1] = ap[8 * LDK];
                a[mt][2] = ap[4];
                a[mt][3] = ap[8 * LDK + 4];
            }
#pragma unroll
            for (int nt = 0; nt < 4; nt++) {
                const unsigned* bp1 = B1b + (wn * 32 + nt * 8 + gid) * LDK + ks * 8 + qid;
                const unsigned* bp3 = B3b + (wn * 32 + nt * 8 + gid) * LDK + ks * 8 + qid;
                unsigned b1[2] = {bp1[0], bp1[4]};
                unsigned b3[2] = {bp3[0], bp3[4]};
#pragma unroll
                for (int mt = 0; mt < 2; mt++) {
                    mma_tf32(cg[mt][nt], a[mt], b1);
                    mma_tf32(cu[mt][nt], a[mt], b3);
                }
            }
        }

        if (kn < HH) {  // store next tile into the other buffer, single barrier
            unsigned* An  = As  + (1 - p) * G1_TM * LDK;
            unsigned* B1n = B1s + (1 - p) * G1_TN * LDK;
            unsigned* B3n = B3s + (1 - p) * G1_TN * LDK;
#pragma unroll
            for (int q = 0; q < 4; q++) {
                int r = lr + 32 * q;
                uint4 v = {f2tf(pa[q].x), f2tf(pa[q].y), f2tf(pa[q].z), f2tf(pa[q].w)};
                *(uint4*)&An[r * LDK + lk] = v;
            }
#pragma unroll
            for (int q = 0; q < 2; q++) {
                int n = lr + 32 * q;
                uint4 v1 = {f2tf(pb1[q].x), f2tf(pb1[q].y), f2tf(pb1[q].z), f2tf(pb1[q].w)};
                uint4 v3 = {f2tf(pb3[q].x), f2tf(pb3[q].y), f2tf(pb3[q].z), f2tf(pb3[q].w)};
                *(uint4*)&B1n[n * LDK + lk] = v1;
                *(uint4*)&B3n[n * LDK + lk] = v3;
            }
            __syncthreads();
            p ^= 1;
        }
    }

    // epilogue: h = gelu(g) * u  (exact gelu), float2 stores
    float* hb = d_hbuf + (size_t)(off + rt) * II + it;
#pragma unroll
    for (int mt = 0; mt < 2; mt++) {
#pragma unroll
        for (int half = 0; half < 2; half++) {
            int r = wm * 32 + mt * 16 + gid + half * 8;
            if (r < rows_valid) {
#pragma unroll
                for (int nt = 0; nt < 4; nt++) {
                    int c = wn * 32 + nt * 8 + 2 * qid;
                    float g0 = cg[mt][nt][half * 2];
                    float g1 = cg[mt][nt][half * 2 + 1];
                    float u0 = cu[mt][nt][half * 2];
                    float u1 = cu[mt][nt][half * 2 + 1];
                    float h0 = 0.5f * g0 * (1.0f + erff(g0 * 0.70710678118654752f)) * u0;
                    float h1 = 0.5f * g1 * (1.0f + erff(g1 * 0.70710678118654752f)) * u1;
                    *(float2*)&hb[(size_t)r * II + c] = make_float2(h0, h1);
                }
            }
        }
    }
}

// ---------------- GEMM 2: y = h @ w2^T, scaled-scatter into out --------------
// 128x128 tile, 8 warps 4(M)x2(N); warp tile 32x64. tf32 mma, fp32 accumulate.
// Each out element receives exactly 2 commutative atomicAdds ->
// bit-deterministic across replays.
__global__ void __launch_bounds__(256)
gemm2_kernel(const float* __restrict__ w2,
             float* __restrict__ out) {
    extern __shared__ unsigned smem_u[];
    unsigned* As = smem_u;                    // [2][G2_TM*LDK]
    unsigned* Bs = As + 2 * G2_TM * LDK;      // [2][G2_TM*LDK]  (N=128 rows)

    int e = blockIdx.z;
    int cnt = d_cnt[e];
    int rt = blockIdx.x * G2_TM;
    if (rt >= cnt) return;
    int ht = blockIdx.y * G2_TN;
    int off = d_off[e];
    int rows_valid = min(G2_TM, cnt - rt);

    int tid = threadIdx.x;
    int lane = tid & 31, warp = tid >> 5;
    int wm = warp >> 1, wn = warp & 1;   // warp tile origin (wm*32, wn*64)
    int gid = lane >> 2, qid = lane & 3;

    int lr = tid >> 3;          // 0..31
    int lk = (tid & 7) * 4;     // 0,4,...,28

    const float* abase = d_hbuf + (size_t)(off + rt) * II;
    const float* bbase = w2 + (size_t)e * HH * II + (size_t)ht * II;

    float cy[2][8][4];
#pragma unroll
    for (int mt = 0; mt < 2; mt++)
#pragma unroll
        for (int nt = 0; nt < 8; nt++)
#pragma unroll
            for (int v = 0; v < 4; v++) cy[mt][nt][v] = 0.f;

    float4 pa[4], pb[4];

    // ---- prefetch + commit tile 0 into buffer 0 ----
#pragma unroll
    for (int q = 0; q < 4; q++) {
        int r = lr + 32 * q;
        pa[q] = (r < rows_valid) ? *(const float4*)&abase[(size_t)r * II + lk]
                                 : make_float4(0.f, 0.f, 0.f, 0.f);
        pb[q] = *(const float4*)&bbase[(size_t)r * II + lk];
    }
#pragma unroll
    for (int q = 0; q < 4; q++) {
        int r = lr + 32 * q;
        uint4 va = {f2tf(pa[q].x), f2tf(pa[q].y), f2tf(pa[q].z), f2tf(pa[q].w)};
        uint4 vb = {f2tf(pb[q].x), f2tf(pb[q].y), f2tf(pb[q].z), f2tf(pb[q].w)};
        *(uint4*)&As[r * LDK + lk] = va;
        *(uint4*)&Bs[r * LDK + lk] = vb;
    }
    __syncthreads();

    int p = 0;
    for (int k0 = 0; k0 < II; k0 += TKT) {
        int kn = k0 + TKT;
        if (kn < II) {
#pragma unroll
            for (int q = 0; q < 4; q++) {
                int r = lr + 32 * q;
                pa[q] = (r < rows_valid)
                      ? *(const float4*)&abase[(size_t)r * II + kn + lk]
                      : make_float4(0.f, 0.f, 0.f, 0.f);
                pb[q] = *(const float4*)&bbase[(size_t)r * II + kn + lk];
            }
        }

        const unsigned* Ab = As + p * G2_TM * LDK;
        const unsigned* Bb = Bs + p * G2_TM * LDK;
#pragma unroll
        for (int ks = 0; ks < TKT / 8; ks++) {
            unsigned a[2][4];
#pragma unroll
            for (int mt = 0; mt < 2; mt++) {
                const unsigned* ap = Ab + (wm * 32 + mt * 16 + gid) * LDK + ks * 8 + qid;
                a[mt][0] = ap[0];
                a[mt][1] = ap[8 * LDK];
                a[mt][2] = ap[4];
                a[mt][3] = ap[8 * LDK + 4];
            }
#pragma unroll
            for (int nt = 0; nt < 8; nt++) {
                const unsigned* bp = Bb + (wn * 64 + nt * 8 + gid) * LDK + ks * 8 + qid;
                unsigned b[2] = {bp[0], bp[4]};
#pragma unroll
                for (int mt = 0; mt < 2; mt++)
                    mma_tf32(cy[mt][nt], a[mt], b);
            }
        }

        if (kn < II) {
            unsigned* An = As + (1 - p) * G2_TM * LDK;
            unsigned* Bn = Bs + (1 - p) * G2_TM * LDK;
#pragma unroll
            for (int q = 0; q < 4; q++) {
                int r = lr + 32 * q;
                uint4 va = {f2tf(pa[q].x), f2tf(pa[q].y), f2tf(pa[q].z), f2tf(pa[q].w)};
                uint4 vb = {f2tf(pb[q].x), f2tf(pb[q].y), f2tf(pb[q].z), f2tf(pb[q].w)};
                *(uint4*)&An[r * LDK + lk] = va;
                *(uint4*)&Bn[r * LDK + lk] = vb;
            }
            __syncthreads();
            p ^= 1;
        }
    }

    // epilogue: scaled scatter (2 commutative atomics per out element total)
#pragma unroll
    for (int mt = 0; mt < 2; mt++) {
#pragma unroll
        for (int half = 0; half < 2; half++) {
            int r = wm * 32 + mt * 16 + gid + half * 8;
            if (r < rows_valid) {
                int grow = off + rt + r;
                int t = d_row_token[grow];
                float w = d_row_w[grow];
#pragma unroll
                for (int nt = 0; nt < 8; nt++) {
                    int c = ht + wn * 64 + nt * 8 + 2 * qid;
                    atomicAdd(&out[(size_t)t * HH + c],     w * cy[mt][nt][half * 2]);
                    atomicAdd(&out[(size_t)t * HH + c + 1], w * cy[mt][nt][half * 2 + 1]);
                }
            }
        }
    }
}

// ---------------- entry point ----------------
extern "C" void kernel_launch(void* const* d_in, const int* in_sizes, int n_in,
                              void* d_out, int out_size) {
    const float* x      = (const float*)d_in[0];
    const float* logits = (const float*)d_in[1];
    const float* scale  = (const float*)d_in[2];
    const float* w13    = (const float*)d_in[3];
    const float* w2     = (const float*)d_in[4];
    float* out = (float*)d_out;

    // Opt in to >48KB dynamic smem. Idempotent, non-stream API (legal under
    // graph capture, not an allocation). Called unconditionally — no static
    // guards per the harness contract.
    cudaFuncSetAttribute(gemm1_kernel,
                         cudaFuncAttributeMaxDynamicSharedMemorySize, G1_SMEM);
    cudaFuncSetAttribute(gemm2_kernel,
                         cudaFuncAttributeMaxDynamicSharedMemorySize, G2_SMEM);

    zero_out_kernel<<<(out_size / 4 + 255) / 256, 256>>>((float4*)out, out_size / 4);
    init_kernel<<<1, 32>>>();
    router_kernel<<<(TT + 255) / 256, 256>>>(logits, scale);
    scan_kernel<<<1, 1>>>();
    assign_kernel<<<(TT + 255) / 256, 256>>>();

    // grid.x covers worst case: one expert holding all 4096 tokens
    gemm1_kernel<<<dim3(TT / G1_TM, II / G1_TN, EE), 256, G1_SMEM>>>(x, w13);
    gemm2_kernel<<<dim3(TT / G2_TM, HH / G2_TN, EE), 256, G2_SMEM>>>(w2, out);
}